// round 1
// baseline (speedup 1.0000x reference)
#include <cuda_runtime.h>
#include <math.h>

// Pair count: G*S = 512*8192 = 4,194,304 (also = in_sizes[2])
#define NPAIRS 4194304

__device__ double g_acc;

__global__ void zero_acc_kernel() {
    g_acc = 0.0;
}

__global__ void __launch_bounds__(256) rgn_loss_kernel(
    const float* __restrict__ inputs,
    const float* __restrict__ target,
    const int*   __restrict__ left,
    const int*   __restrict__ right,
    int npairs)
{
    int i = blockIdx.x * blockDim.x + threadIdx.x;
    float val = 0.0f;
    if (i < npairs) {
        int l = left[i];
        int r = right[i];
        // row 1 (CA) of the 3x3 at point idx: offset idx*9 + 3
        const float* al = inputs + (size_t)l * 9 + 3;
        const float* ar = inputs + (size_t)r * 9 + 3;
        const float* tl = target + (size_t)l * 9 + 3;
        const float* tr = target + (size_t)r * 9 + 3;

        float dx = al[0] - ar[0];
        float dy = al[1] - ar[1];
        float dz = al[2] - ar[2];
        float d_in = sqrtf(fmaf(dx, dx, fmaf(dy, dy, dz * dz)));

        float ex = tl[0] - tr[0];
        float ey = tl[1] - tr[1];
        float ez = tl[2] - tr[2];
        float d_tg = sqrtf(fmaf(ex, ex, fmaf(ey, ey, ez * ez)));

        float t = d_in - d_tg;
        val = t * t;
    }

    // warp reduce
    #pragma unroll
    for (int off = 16; off > 0; off >>= 1)
        val += __shfl_down_sync(0xFFFFFFFFu, val, off);

    __shared__ float warp_sums[8];
    int lane = threadIdx.x & 31;
    int wid  = threadIdx.x >> 5;
    if (lane == 0) warp_sums[wid] = val;
    __syncthreads();

    if (wid == 0) {
        float s = (lane < 8) ? warp_sums[lane] : 0.0f;
        #pragma unroll
        for (int off = 4; off > 0; off >>= 1)
            s += __shfl_down_sync(0xFFFFFFFFu, s, off);
        if (lane == 0)
            atomicAdd(&g_acc, (double)s);
    }
}

__global__ void finalize_kernel(float* out, int npairs) {
    out[0] = (float)(g_acc / (double)npairs);
}

extern "C" void kernel_launch(void* const* d_in, const int* in_sizes, int n_in,
                              void* d_out, int out_size) {
    const float* inputs = (const float*)d_in[0];
    const float* target = (const float*)d_in[1];
    const int*   left   = (const int*)d_in[2];
    const int*   right  = (const int*)d_in[3];
    float* out = (float*)d_out;

    int npairs = in_sizes[2];

    zero_acc_kernel<<<1, 1>>>();

    int threads = 256;
    int blocks = (npairs + threads - 1) / threads;
    rgn_loss_kernel<<<blocks, threads>>>(inputs, target, left, right, npairs);

    finalize_kernel<<<1, 1>>>(out, npairs);
}

// round 2
// speedup vs baseline: 1.0043x; 1.0043x over previous
#include <cuda_runtime.h>
#include <math.h>

// npairs = 4,194,304 ; PAIRS_PER_THREAD=4, 256 thr/block -> 4096 blocks
#define TPB 256
#define PPT 4

__device__ double g_acc = 0.0;
__device__ unsigned int g_count = 0;

__global__ void __launch_bounds__(TPB) rgn_loss_fused_kernel(
    const float* __restrict__ inputs,
    const float* __restrict__ target,
    const int*   __restrict__ left,
    const int*   __restrict__ right,
    int npairs, float* __restrict__ out)
{
    const int base = (blockIdx.x * TPB + threadIdx.x) * PPT;

    float acc = 0.0f;
    if (base + PPT <= npairs) {
        const int4 L = *reinterpret_cast<const int4*>(left + base);
        const int4 R = *reinterpret_cast<const int4*>(right + base);
        const int ls[PPT] = {L.x, L.y, L.z, L.w};
        const int rs[PPT] = {R.x, R.y, R.z, R.w};

        // Load phase: issue all 48 gather loads before any compute so ptxas
        // front-batches them (max MLP).
        float ax[PPT][3], bx[PPT][3], cx[PPT][3], dx_[PPT][3];
        #pragma unroll
        for (int j = 0; j < PPT; j++) {
            const float* al = inputs + (size_t)ls[j] * 9 + 3;
            const float* ar = inputs + (size_t)rs[j] * 9 + 3;
            const float* tl = target + (size_t)ls[j] * 9 + 3;
            const float* tr = target + (size_t)rs[j] * 9 + 3;
            #pragma unroll
            for (int k = 0; k < 3; k++) {
                ax[j][k]  = al[k];
                bx[j][k]  = ar[k];
                cx[j][k]  = tl[k];
                dx_[j][k] = tr[k];
            }
        }

        #pragma unroll
        for (int j = 0; j < PPT; j++) {
            float ux = ax[j][0] - bx[j][0];
            float uy = ax[j][1] - bx[j][1];
            float uz = ax[j][2] - bx[j][2];
            float d_in = sqrtf(fmaf(ux, ux, fmaf(uy, uy, uz * uz)));

            float vx = cx[j][0] - dx_[j][0];
            float vy = cx[j][1] - dx_[j][1];
            float vz = cx[j][2] - dx_[j][2];
            float d_tg = sqrtf(fmaf(vx, vx, fmaf(vy, vy, vz * vz)));

            float t = d_in - d_tg;
            acc = fmaf(t, t, acc);
        }
    } else {
        for (int j = 0; j < PPT; j++) {
            int i = base + j;
            if (i < npairs) {
                int l = left[i], r = right[i];
                const float* al = inputs + (size_t)l * 9 + 3;
                const float* ar = inputs + (size_t)r * 9 + 3;
                const float* tl = target + (size_t)l * 9 + 3;
                const float* tr = target + (size_t)r * 9 + 3;
                float ux = al[0]-ar[0], uy = al[1]-ar[1], uz = al[2]-ar[2];
                float vx = tl[0]-tr[0], vy = tl[1]-tr[1], vz = tl[2]-tr[2];
                float d_in = sqrtf(fmaf(ux,ux,fmaf(uy,uy,uz*uz)));
                float d_tg = sqrtf(fmaf(vx,vx,fmaf(vy,vy,vz*vz)));
                float t = d_in - d_tg;
                acc = fmaf(t, t, acc);
            }
        }
    }

    // warp reduce
    #pragma unroll
    for (int off = 16; off > 0; off >>= 1)
        acc += __shfl_down_sync(0xFFFFFFFFu, acc, off);

    __shared__ float warp_sums[TPB / 32];
    const int lane = threadIdx.x & 31;
    const int wid  = threadIdx.x >> 5;
    if (lane == 0) warp_sums[wid] = acc;
    __syncthreads();

    if (wid == 0) {
        float s = (lane < TPB / 32) ? warp_sums[lane] : 0.0f;
        #pragma unroll
        for (int off = (TPB / 64); off > 0; off >>= 1)
            s += __shfl_down_sync(0xFFFFFFFFu, s, off);

        if (lane == 0) {
            atomicAdd(&g_acc, (double)s);
            __threadfence();
            unsigned int done = atomicAdd(&g_count, 1u);
            if (done == gridDim.x - 1) {
                // last block: all adds visible
                out[0] = (float)(g_acc / (double)npairs);
                // reset for next (graph-replayed) launch
                g_acc = 0.0;
                g_count = 0;
            }
        }
    }
}

extern "C" void kernel_launch(void* const* d_in, const int* in_sizes, int n_in,
                              void* d_out, int out_size) {
    const float* inputs = (const float*)d_in[0];
    const float* target = (const float*)d_in[1];
    const int*   left   = (const int*)d_in[2];
    const int*   right  = (const int*)d_in[3];
    float* out = (float*)d_out;

    int npairs = in_sizes[2];
    int blocks = (npairs + TPB * PPT - 1) / (TPB * PPT);

    rgn_loss_fused_kernel<<<blocks, TPB>>>(inputs, target, left, right, npairs, out);
}